// round 1
// baseline (speedup 1.0000x reference)
#include <cuda_runtime.h>
#include <math_constants.h>

// Problem: inputs [B=64, H=56, W=56, C=256] f32, NHWC.
// Output:  max over (H,W) -> [B=64, C=256] f32.
//
// Strategy: HBM-bound streaming reduce.
//   Kernel 1: grid = B * SPLIT blocks (64*16 = 1024), 256 threads each.
//             Each block reduces a 196-position spatial slice for all 256
//             channels (64 float4 channel-groups). Thread t handles channel
//             group (t%64) and spatial phase (t/64); 49 float4 loads each,
//             fully coalesced (warp = 32 consecutive float4 = 512B).
//             Cross-phase reduce via smem; partials to __device__ scratch.
//   Kernel 2: 16384 threads reduce the 16 partials per (b,c).

#define B_DIM   64
#define HW      3136          // 56*56
#define C_DIM   256
#define CG      64            // float4 channel groups (256/4)
#define SPLIT   16
#define SPAN    (HW / SPLIT)  // 196 spatial positions per block
#define PHASES  4             // 256 threads / 64 channel groups
#define ITERS   (SPAN / PHASES) // 49

__device__ float4 g_partial[B_DIM * SPLIT * CG];  // 1 MB scratch

__global__ __launch_bounds__(256, 8)
void spatial_max_partial(const float* __restrict__ in) {
    const int blk   = blockIdx.x;          // 0 .. 1023
    const int b     = blk >> 4;            // batch
    const int split = blk & (SPLIT - 1);   // spatial slice
    const int t     = threadIdx.x;
    const int cg    = t & (CG - 1);        // channel float4 group
    const int sp    = t >> 6;              // spatial phase 0..3

    // Base: spatial position (split*SPAN + sp), channel group cg.
    const float4* __restrict__ base =
        reinterpret_cast<const float4*>(in)
        + (size_t)(b * HW + split * SPAN + sp) * CG + cg;

    float4 m = make_float4(-CUDART_INF_F, -CUDART_INF_F,
                           -CUDART_INF_F, -CUDART_INF_F);

    // 49 independent float4 loads, stride PHASES*CG float4s.
    #pragma unroll 7
    for (int i = 0; i < ITERS; ++i) {
        float4 v = __ldg(base + (size_t)i * (PHASES * CG));
        m.x = fmaxf(m.x, v.x);
        m.y = fmaxf(m.y, v.y);
        m.z = fmaxf(m.z, v.z);
        m.w = fmaxf(m.w, v.w);
    }

    __shared__ float4 smem[256];
    smem[t] = m;
    __syncthreads();

    if (sp == 0) {
        float4 a = smem[cg];
        float4 p = smem[cg + 64];
        float4 q = smem[cg + 128];
        float4 r = smem[cg + 192];
        a.x = fmaxf(fmaxf(a.x, p.x), fmaxf(q.x, r.x));
        a.y = fmaxf(fmaxf(a.y, p.y), fmaxf(q.y, r.y));
        a.z = fmaxf(fmaxf(a.z, p.z), fmaxf(q.z, r.z));
        a.w = fmaxf(fmaxf(a.w, p.w), fmaxf(q.w, r.w));
        g_partial[blk * CG + cg] = a;
    }
}

__global__ __launch_bounds__(256)
void spatial_max_final(float* __restrict__ out) {
    const int idx = blockIdx.x * blockDim.x + threadIdx.x;  // 0 .. 16383
    const int b   = idx >> 8;          // batch
    const int c   = idx & (C_DIM - 1); // channel

    const float* part = reinterpret_cast<const float*>(g_partial);
    float m = -CUDART_INF_F;
    #pragma unroll
    for (int s = 0; s < SPLIT; ++s) {
        m = fmaxf(m, part[((b * SPLIT + s) << 8) + c]);
    }
    out[idx] = m;
}

extern "C" void kernel_launch(void* const* d_in, const int* in_sizes, int n_in,
                              void* d_out, int out_size) {
    const float* in  = (const float*)d_in[0];
    float*       out = (float*)d_out;

    spatial_max_partial<<<B_DIM * SPLIT, 256>>>(in);
    spatial_max_final<<<(B_DIM * C_DIM) / 256, 256>>>(out);
}